// round 1
// baseline (speedup 1.0000x reference)
#include <cuda_runtime.h>

#define T_STEPS 512
#define BATCH   256
#define NH      512
#define NH2     256
#define NU      32
#define NY      64
#define TT      16

// 269 MB scratch for X = [513, 256, 512] fp32 (static __device__: allocation-guard safe)
__device__ float g_X[(size_t)(T_STEPS + 1) * BATCH * NH];

// ---------- packed f32x2 helpers (ptxas never auto-packs FFMA2) ----------
__device__ __forceinline__ unsigned long long pack2(float lo, float hi) {
    unsigned long long r;
    asm("mov.b64 %0, {%1, %2};" : "=l"(r) : "f"(lo), "f"(hi));
    return r;
}
__device__ __forceinline__ void unpack2(unsigned long long v, float& lo, float& hi) {
    asm("mov.b64 {%0, %1}, %2;" : "=f"(lo), "=f"(hi) : "l"(v));
}
__device__ __forceinline__ unsigned long long fma2(unsigned long long a,
                                                   unsigned long long b,
                                                   unsigned long long c) {
    unsigned long long d;
    asm("fma.rn.f32x2 %0, %1, %2, %3;" : "=l"(d) : "l"(a), "l"(b), "l"(c));
    return d;
}
__device__ __forceinline__ unsigned long long dup2(float v) { return pack2(v, v); }

// ---------------- K1: x0 = y0 @ W_y2x^T + b_y2x  ->  g_X[0] ----------------
__global__ void k1_x0(const float* __restrict__ y0,
                      const float* __restrict__ Wyx,
                      const float* __restrict__ byx) {
    __shared__ float ys[NY];
    const int b = blockIdx.x;
    const int h = threadIdx.x;          // 512 threads
    if (h < NY) ys[h] = y0[b * NY + h];
    __syncthreads();
    const float4* wr = (const float4*)(Wyx + h * NY);
    float acc = byx[h];
#pragma unroll
    for (int q = 0; q < NY / 4; q++) {
        float4 w = wr[q];
        acc = fmaf(w.x, ys[4 * q + 0], acc);
        acc = fmaf(w.y, ys[4 * q + 1], acc);
        acc = fmaf(w.z, ys[4 * q + 2], acc);
        acc = fmaf(w.w, ys[4 * q + 3], acc);
    }
    g_X[(size_t)b * NH + h] = acc;
}

// ------- K2: fused Bu = U@B^T + complex-diagonal scan, writes X[1..512] -------
// CTA = one batch element, thread h2 owns channel pair (h2, h2+256).
__global__ void __launch_bounds__(NH2)
k2_scan(const float* __restrict__ U,
        const float* __restrict__ lr_,
        const float* __restrict__ li_,
        const float* __restrict__ B) {
    __shared__ unsigned long long Us2[TT][NU];   // U value duplicated into both f32x2 lanes
    const int b  = blockIdx.x;
    const int h2 = threadIdx.x;                  // 256 threads

    // B rows for the pair, packed (re, im) per u
    unsigned long long bb2[NU];
    const float* brp = B + (size_t)h2 * NU;
    const float* bip = B + (size_t)(h2 + NH2) * NU;
#pragma unroll
    for (int q = 0; q < NU / 4; q++) {
        float4 r = *(const float4*)(brp + 4 * q);
        float4 i = *(const float4*)(bip + 4 * q);
        bb2[4 * q + 0] = pack2(r.x, i.x);
        bb2[4 * q + 1] = pack2(r.y, i.y);
        bb2[4 * q + 2] = pack2(r.z, i.z);
        bb2[4 * q + 3] = pack2(r.w, i.w);
    }
    const float lr = lr_[h2];
    const float li = li_[h2];
    float xr = g_X[(size_t)b * NH + h2];
    float xi = g_X[(size_t)b * NH + NH2 + h2];

    for (int t0 = 0; t0 < T_STEPS; t0 += TT) {
        __syncthreads();
        // stage TT steps of U[t][b][:] (512 floats, 2 per thread), duplicated
#pragma unroll
        for (int r = 0; r < (TT * NU) / NH2; r++) {
            int i  = h2 + NH2 * r;
            int tt = i >> 5;
            int u  = i & 31;
            float v = U[((size_t)(t0 + tt) * BATCH + b) * NU + u];
            Us2[tt][u] = pack2(v, v);
        }
        __syncthreads();
#pragma unroll 4
        for (int tt = 0; tt < TT; tt++) {
            unsigned long long accA = 0ULL, accB = 0ULL;  // two chains for ILP
#pragma unroll
            for (int u = 0; u < NU; u += 2) {
                accA = fma2(Us2[tt][u + 0], bb2[u + 0], accA);
                accB = fma2(Us2[tt][u + 1], bb2[u + 1], accB);
            }
            float ar, ai, br_, bi_;
            unpack2(accA, ar, ai);
            unpack2(accB, br_, bi_);
            const float bur = ar + br_;
            const float bui = ai + bi_;
            const float nr = fmaf(lr, xr, fmaf(-li, xi, bur));
            const float ni = fmaf(li, xr, fmaf(lr, xi, bui));
            xr = nr; xi = ni;
            float* Xo = g_X + ((size_t)(t0 + tt + 1) * BATCH + b) * NH;
            Xo[h2]        = xr;
            Xo[NH2 + h2]  = xi;
        }
    }
}

// ---------------- K3: Y = X @ W_x2y^T + b  (per-t 256x64x512 GEMM) ----------------
// CTA = one timestep t (256 rows). 256 threads, 8(m)x8(n) register tiles,
// m packed in pairs into f32x2. smem double-staged via register prefetch.
__global__ void __launch_bounds__(256, 2)
k3_out(const float* __restrict__ W,       // [NY][NH]
       const float* __restrict__ bias,    // [NY]
       float* __restrict__ Y) {
    __shared__ float sx[16][256];
    __shared__ float sw[16][68];          // padded
    const int t   = blockIdx.x;
    const int tid = threadIdx.x;
    const int tm  = tid >> 3;             // 0..31 : m-tile (8 rows)
    const int tn  = tid & 7;              // 0..7  : n-tile (8 cols)
    const int wn  = tid >> 2;             // 0..63 : W row for loads
    const int wk  = tid & 3;              // k-quarter for loads

    const float* Xp = g_X + (size_t)t * (BATCH * NH) + (size_t)tid * NH;
    const float* Wp = W + (size_t)wn * NH + wk * 4;

    unsigned long long acc[4][8];
#pragma unroll
    for (int i = 0; i < 4; i++)
#pragma unroll
        for (int j = 0; j < 8; j++) acc[i][j] = 0ULL;

    // prefetch chunk 0
    float4 xa0 = *(const float4*)(Xp + 0);
    float4 xa1 = *(const float4*)(Xp + 4);
    float4 xa2 = *(const float4*)(Xp + 8);
    float4 xa3 = *(const float4*)(Xp + 12);
    float4 wa  = *(const float4*)(Wp);

#pragma unroll 1
    for (int c = 0; c < NH / 16; c++) {
        // stage current chunk
        sx[0][tid] = xa0.x; sx[1][tid] = xa0.y; sx[2][tid] = xa0.z; sx[3][tid] = xa0.w;
        sx[4][tid] = xa1.x; sx[5][tid] = xa1.y; sx[6][tid] = xa1.z; sx[7][tid] = xa1.w;
        sx[8][tid] = xa2.x; sx[9][tid] = xa2.y; sx[10][tid] = xa2.z; sx[11][tid] = xa2.w;
        sx[12][tid] = xa3.x; sx[13][tid] = xa3.y; sx[14][tid] = xa3.z; sx[15][tid] = xa3.w;
        sw[wk * 4 + 0][wn] = wa.x;
        sw[wk * 4 + 1][wn] = wa.y;
        sw[wk * 4 + 2][wn] = wa.z;
        sw[wk * 4 + 3][wn] = wa.w;
        __syncthreads();
        if (c + 1 < NH / 16) {           // prefetch next chunk into registers
            const float* xp = Xp + (c + 1) * 16;
            xa0 = *(const float4*)(xp + 0);
            xa1 = *(const float4*)(xp + 4);
            xa2 = *(const float4*)(xp + 8);
            xa3 = *(const float4*)(xp + 12);
            wa  = *(const float4*)(Wp + (c + 1) * 16);
        }
#pragma unroll
        for (int k = 0; k < 16; k++) {
            unsigned long long a0 = *(const unsigned long long*)&sx[k][tm * 8 + 0];
            unsigned long long a1 = *(const unsigned long long*)&sx[k][tm * 8 + 2];
            unsigned long long a2 = *(const unsigned long long*)&sx[k][tm * 8 + 4];
            unsigned long long a3 = *(const unsigned long long*)&sx[k][tm * 8 + 6];
            float4 w0 = *(const float4*)&sw[k][tn * 8 + 0];
            float4 w1 = *(const float4*)&sw[k][tn * 8 + 4];
            unsigned long long b0 = dup2(w0.x), b1 = dup2(w0.y);
            unsigned long long b2 = dup2(w0.z), b3 = dup2(w0.w);
            unsigned long long b4 = dup2(w1.x), b5 = dup2(w1.y);
            unsigned long long b6 = dup2(w1.z), b7 = dup2(w1.w);
            acc[0][0] = fma2(a0, b0, acc[0][0]); acc[0][1] = fma2(a0, b1, acc[0][1]);
            acc[0][2] = fma2(a0, b2, acc[0][2]); acc[0][3] = fma2(a0, b3, acc[0][3]);
            acc[0][4] = fma2(a0, b4, acc[0][4]); acc[0][5] = fma2(a0, b5, acc[0][5]);
            acc[0][6] = fma2(a0, b6, acc[0][6]); acc[0][7] = fma2(a0, b7, acc[0][7]);
            acc[1][0] = fma2(a1, b0, acc[1][0]); acc[1][1] = fma2(a1, b1, acc[1][1]);
            acc[1][2] = fma2(a1, b2, acc[1][2]); acc[1][3] = fma2(a1, b3, acc[1][3]);
            acc[1][4] = fma2(a1, b4, acc[1][4]); acc[1][5] = fma2(a1, b5, acc[1][5]);
            acc[1][6] = fma2(a1, b6, acc[1][6]); acc[1][7] = fma2(a1, b7, acc[1][7]);
            acc[2][0] = fma2(a2, b0, acc[2][0]); acc[2][1] = fma2(a2, b1, acc[2][1]);
            acc[2][2] = fma2(a2, b2, acc[2][2]); acc[2][3] = fma2(a2, b3, acc[2][3]);
            acc[2][4] = fma2(a2, b4, acc[2][4]); acc[2][5] = fma2(a2, b5, acc[2][5]);
            acc[2][6] = fma2(a2, b6, acc[2][6]); acc[2][7] = fma2(a2, b7, acc[2][7]);
            acc[3][0] = fma2(a3, b0, acc[3][0]); acc[3][1] = fma2(a3, b1, acc[3][1]);
            acc[3][2] = fma2(a3, b2, acc[3][2]); acc[3][3] = fma2(a3, b3, acc[3][3]);
            acc[3][4] = fma2(a3, b4, acc[3][4]); acc[3][5] = fma2(a3, b5, acc[3][5]);
            acc[3][6] = fma2(a3, b6, acc[3][6]); acc[3][7] = fma2(a3, b7, acc[3][7]);
        }
        __syncthreads();
    }

    // epilogue: add bias, write 2 rows per m-pair as float4s
    float bj[8];
#pragma unroll
    for (int j = 0; j < 8; j++) bj[j] = bias[tn * 8 + j];
#pragma unroll
    for (int i2 = 0; i2 < 4; i2++) {
        float r0[8], r1[8];
#pragma unroll
        for (int j = 0; j < 8; j++) {
            float lo, hi;
            unpack2(acc[i2][j], lo, hi);
            r0[j] = lo + bj[j];
            r1[j] = hi + bj[j];
        }
        const int m0 = tm * 8 + 2 * i2;
        size_t base = ((size_t)t * BATCH + m0) * NY + tn * 8;
        *(float4*)&Y[base + 0]      = make_float4(r0[0], r0[1], r0[2], r0[3]);
        *(float4*)&Y[base + 4]      = make_float4(r0[4], r0[5], r0[6], r0[7]);
        *(float4*)&Y[base + NY + 0] = make_float4(r1[0], r1[1], r1[2], r1[3]);
        *(float4*)&Y[base + NY + 4] = make_float4(r1[4], r1[5], r1[6], r1[7]);
    }
}

extern "C" void kernel_launch(void* const* d_in, const int* in_sizes, int n_in,
                              void* d_out, int out_size) {
    (void)in_sizes; (void)n_in; (void)out_size;
    const float* y0  = (const float*)d_in[0];
    const float* U   = (const float*)d_in[1];
    const float* lr  = (const float*)d_in[2];
    const float* li  = (const float*)d_in[3];
    const float* B   = (const float*)d_in[4];
    const float* Wyx = (const float*)d_in[5];
    const float* byx = (const float*)d_in[6];
    const float* Wxy = (const float*)d_in[7];
    const float* bxy = (const float*)d_in[8];
    float* Y = (float*)d_out;

    k1_x0<<<BATCH, NH>>>(y0, Wyx, byx);
    k2_scan<<<BATCH, NH2>>>(U, lr, li, B);
    k3_out<<<T_STEPS + 1, 256>>>(Wxy, bxy, Y);
}

// round 3
// speedup vs baseline: 1.5819x; 1.5819x over previous
#include <cuda_runtime.h>
#include <cuda_bf16.h>
#include <cstdint>

#define T_STEPS 512
#define BATCH   256
#define NH      512
#define NH2     256
#define NU      32
#define NY      64
#define TT      16

// X split-bf16 planes: Xh = bf16(x), Xl = bf16(x - float(Xh))
__device__ __nv_bfloat16 g_Xh[(size_t)(T_STEPS + 1) * BATCH * NH];
__device__ __nv_bfloat16 g_Xl[(size_t)(T_STEPS + 1) * BATCH * NH];
__device__ __nv_bfloat16 g_Wh[NY * NH];
__device__ __nv_bfloat16 g_Wl[NY * NH];

// ===================== helpers =====================
__device__ __forceinline__ uint32_t smem_u32(const void* p) {
    uint32_t a;
    asm("{ .reg .u64 t; cvta.to.shared.u64 t, %1; cvt.u32.u64 %0, t; }" : "=r"(a) : "l"(p));
    return a;
}
__device__ __forceinline__ unsigned long long pack2(float lo, float hi) {
    unsigned long long r;
    asm("mov.b64 %0, {%1, %2};" : "=l"(r) : "f"(lo), "f"(hi));
    return r;
}
__device__ __forceinline__ void unpack2(unsigned long long v, float& lo, float& hi) {
    asm("mov.b64 {%0, %1}, %2;" : "=f"(lo), "=f"(hi) : "l"(v));
}
__device__ __forceinline__ unsigned long long fma2(unsigned long long a,
                                                   unsigned long long b,
                                                   unsigned long long c) {
    unsigned long long d;
    asm("fma.rn.f32x2 %0, %1, %2, %3;" : "=l"(d) : "l"(a), "l"(b), "l"(c));
    return d;
}
__device__ __forceinline__ unsigned long long dup2(float v) { return pack2(v, v); }

__device__ __forceinline__ void split_bf16(float x, __nv_bfloat16& h, __nv_bfloat16& l) {
    h = __float2bfloat16_rn(x);
    l = __float2bfloat16_rn(x - __bfloat162float(h));
}

__device__ __forceinline__ void cpa16(uint32_t dst, const void* src) {
    asm volatile("cp.async.cg.shared.global [%0], [%1], 16;" :: "r"(dst), "l"(src));
}
__device__ __forceinline__ void cp_commit() {
    asm volatile("cp.async.commit_group;" ::: "memory");
}
template <int N>
__device__ __forceinline__ void cp_wait() {
    asm volatile("cp.async.wait_group %0;" :: "n"(N) : "memory");
}
__device__ __forceinline__ void ldsm4(uint32_t& r0, uint32_t& r1, uint32_t& r2, uint32_t& r3,
                                      uint32_t addr) {
    asm volatile("ldmatrix.sync.aligned.m8n8.x4.shared.b16 {%0,%1,%2,%3}, [%4];"
                 : "=r"(r0), "=r"(r1), "=r"(r2), "=r"(r3) : "r"(addr));
}
__device__ __forceinline__ void mma16816(float* c, const uint32_t* a, const uint32_t* b) {
    asm volatile(
        "mma.sync.aligned.m16n8k16.row.col.f32.bf16.bf16.f32 "
        "{%0,%1,%2,%3}, {%4,%5,%6,%7}, {%8,%9}, {%0,%1,%2,%3};"
        : "+f"(c[0]), "+f"(c[1]), "+f"(c[2]), "+f"(c[3])
        : "r"(a[0]), "r"(a[1]), "r"(a[2]), "r"(a[3]), "r"(b[0]), "r"(b[1]));
}

// ========== K0: split W_x2y (fp32) into bf16 hi/lo planes ==========
__global__ void k0_wsplit(const float* __restrict__ W) {
    for (int i = blockIdx.x * blockDim.x + threadIdx.x; i < NY * NH;
         i += gridDim.x * blockDim.x) {
        __nv_bfloat16 h, l;
        split_bf16(W[i], h, l);
        g_Wh[i] = h;
        g_Wl[i] = l;
    }
}

// ========== K2: x0 + fused Bu einsum + complex-diagonal scan -> split-bf16 X ==========
// grid = (b, chalf): 512 CTAs x 128 threads; thread owns channel pair (h2, h2+256).
__global__ void __launch_bounds__(128)
k2_scan(const float* __restrict__ U,
        const float* __restrict__ lr_,
        const float* __restrict__ li_,
        const float* __restrict__ B,
        const float* __restrict__ y0,
        const float* __restrict__ Wyx,
        const float* __restrict__ byx) {
    __shared__ unsigned long long Us2[TT][NU];
    __shared__ float ys[NY];
    const int b     = blockIdx.x >> 1;
    const int chalf = blockIdx.x & 1;
    const int tid   = threadIdx.x;
    const int h2    = chalf * 128 + tid;

    // ---- x0 = y0 @ Wyx^T + byx for pair (h2, h2+256), packed f32x2 ----
    if (tid < NY) ys[tid] = y0[b * NY + tid];
    __syncthreads();
    unsigned long long acc0 = pack2(byx[h2], byx[h2 + NH2]);
    {
        const float4* wr = (const float4*)(Wyx + (size_t)h2 * NY);
        const float4* wi = (const float4*)(Wyx + (size_t)(h2 + NH2) * NY);
#pragma unroll
        for (int q = 0; q < NY / 4; q++) {
            float4 a = wr[q], c = wi[q];
            acc0 = fma2(pack2(a.x, c.x), dup2(ys[4 * q + 0]), acc0);
            acc0 = fma2(pack2(a.y, c.y), dup2(ys[4 * q + 1]), acc0);
            acc0 = fma2(pack2(a.z, c.z), dup2(ys[4 * q + 2]), acc0);
            acc0 = fma2(pack2(a.w, c.w), dup2(ys[4 * q + 3]), acc0);
        }
    }
    float xr, xi;
    unpack2(acc0, xr, xi);
    {
        size_t idx = (size_t)b * NH;
        __nv_bfloat16 hr, lr2, hi_, li2;
        split_bf16(xr, hr, lr2);
        split_bf16(xi, hi_, li2);
        g_Xh[idx + h2] = hr;        g_Xl[idx + h2] = lr2;
        g_Xh[idx + NH2 + h2] = hi_; g_Xl[idx + NH2 + h2] = li2;
    }

    // ---- B rows packed (re, im) ----
    unsigned long long bb2[NU];
    const float* brp = B + (size_t)h2 * NU;
    const float* bip = B + (size_t)(h2 + NH2) * NU;
#pragma unroll
    for (int q = 0; q < NU / 4; q++) {
        float4 r = *(const float4*)(brp + 4 * q);
        float4 i = *(const float4*)(bip + 4 * q);
        bb2[4 * q + 0] = pack2(r.x, i.x);
        bb2[4 * q + 1] = pack2(r.y, i.y);
        bb2[4 * q + 2] = pack2(r.z, i.z);
        bb2[4 * q + 3] = pack2(r.w, i.w);
    }
    const float lam_r = lr_[h2];
    const float lam_i = li_[h2];

    for (int t0 = 0; t0 < T_STEPS; t0 += TT) {
        __syncthreads();
#pragma unroll
        for (int r = 0; r < (TT * NU) / 128; r++) {      // 4 loads per thread
            int i  = tid + 128 * r;
            int tt = i >> 5;
            int u  = i & 31;
            float v = U[((size_t)(t0 + tt) * BATCH + b) * NU + u];
            Us2[tt][u] = pack2(v, v);
        }
        __syncthreads();
#pragma unroll 4
        for (int tt = 0; tt < TT; tt++) {
            unsigned long long accA = 0ULL, accB = 0ULL;
#pragma unroll
            for (int u = 0; u < NU; u += 2) {
                accA = fma2(Us2[tt][u + 0], bb2[u + 0], accA);
                accB = fma2(Us2[tt][u + 1], bb2[u + 1], accB);
            }
            float ar, ai, br_, bi_;
            unpack2(accA, ar, ai);
            unpack2(accB, br_, bi_);
            const float bur = ar + br_;
            const float bui = ai + bi_;
            const float nr = fmaf(lam_r, xr, fmaf(-lam_i, xi, bur));
            const float ni = fmaf(lam_i, xr, fmaf(lam_r, xi, bui));
            xr = nr; xi = ni;
            size_t idx = ((size_t)(t0 + tt + 1) * BATCH + b) * NH;
            __nv_bfloat16 hr, lr2, hi_, li2;
            split_bf16(xr, hr, lr2);
            split_bf16(xi, hi_, li2);
            g_Xh[idx + h2] = hr;        g_Xl[idx + h2] = lr2;
            g_Xh[idx + NH2 + h2] = hi_; g_Xl[idx + NH2 + h2] = li2;
        }
    }
}

// ========== K3: HMMA bf16x3 GEMM: Y[t, 128-half, 64] = X @ W^T + bias ==========
#define KC        64
#define NCH       8
#define A_STRIDE  144      // bytes per 64-bf16 row (+16 pad: conflict-free ldmatrix)
#define SM_BIAS   0
#define SM_AH(s)  (512 + (s) * 55296)
#define SM_AL(s)  (SM_AH(s) + 18432)
#define SM_WH(s)  (SM_AH(s) + 36864)
#define SM_WL(s)  (SM_AH(s) + 46080)
#define SMEM_K3   (512 + 2 * 55296)

__global__ void __launch_bounds__(128, 2)
k3_mma(const float* __restrict__ bias, float* __restrict__ Y) {
    extern __shared__ char smem[];
    const uint32_t sb = smem_u32(smem);
    const int tid  = threadIdx.x;
    const int wid  = tid >> 5;
    const int lane = tid & 31;
    const int t    = blockIdx.x >> 1;
    const int half = blockIdx.x & 1;

    float* s_bias = (float*)(smem + SM_BIAS);
    if (tid < NY) s_bias[tid] = bias[tid];

    const size_t Abase = ((size_t)t * BATCH + half * 128) * NH;
    const int lrow = tid >> 3;      // staging row-in-group
    const int lseg = tid & 7;       // 16B segment

    // ---- staging lambda (chunk c into stage s) ----
    auto stage_load = [&](int c) {
        const int s = c & 1;
        const __nv_bfloat16* ah = g_Xh + Abase + c * KC;
        const __nv_bfloat16* al = g_Xl + Abase + c * KC;
#pragma unroll
        for (int p = 0; p < 8; p++) {
            int row = p * 16 + lrow;
            uint32_t d = row * A_STRIDE + lseg * 16;
            cpa16(sb + SM_AH(s) + d, ah + (size_t)row * NH + lseg * 8);
            cpa16(sb + SM_AL(s) + d, al + (size_t)row * NH + lseg * 8);
        }
        const __nv_bfloat16* wh = g_Wh + c * KC;
        const __nv_bfloat16* wl = g_Wl + c * KC;
#pragma unroll
        for (int p = 0; p < 4; p++) {
            int row = p * 16 + lrow;
            uint32_t d = row * A_STRIDE + lseg * 16;
            cpa16(sb + SM_WH(s) + d, wh + (size_t)row * NH + lseg * 8);
            cpa16(sb + SM_WL(s) + d, wl + (size_t)row * NH + lseg * 8);
        }
        cp_commit();
    };

    float acc[2][8][4];
#pragma unroll
    for (int mt = 0; mt < 2; mt++)
#pragma unroll
        for (int nt = 0; nt < 8; nt++)
#pragma unroll
            for (int e = 0; e < 4; e++) acc[mt][nt][e] = 0.0f;

    // ldmatrix lane addressing (byte offsets within a stage, before +ks*32)
    const int arow = wid * 32 + (lane & 15);
    const int akb  = (lane >> 4) * 16;
    const uint32_t aOff = arow * A_STRIDE + akb;
    const int wmat = lane >> 3;
    const int wrow_in = (lane & 7) + ((wmat >> 1) << 3);   // row within 16-row group
    const int wkb  = (wmat & 1) * 16;
    const uint32_t wOff = wrow_in * A_STRIDE + wkb;

    stage_load(0);

#pragma unroll 1
    for (int c = 0; c < NCH; c++) {
        const int s = c & 1;
        if (c + 1 < NCH) { stage_load(c + 1); cp_wait<1>(); }
        else             { cp_wait<0>(); }
        __syncthreads();

#pragma unroll
        for (int ks = 0; ks < 4; ks++) {
            const uint32_t ko = ks * 32;
            uint32_t ahf[2][4], alf[2][4];
#pragma unroll
            for (int mt = 0; mt < 2; mt++) {
                uint32_t aA = sb + SM_AH(s) + aOff + mt * (16 * A_STRIDE) + ko;
                ldsm4(ahf[mt][0], ahf[mt][1], ahf[mt][2], ahf[mt][3], aA);
                uint32_t aL = sb + SM_AL(s) + aOff + mt * (16 * A_STRIDE) + ko;
                ldsm4(alf[mt][0], alf[mt][1], alf[mt][2], alf[mt][3], aL);
            }
            uint32_t whf[8][2], wlf[8][2];
#pragma unroll
            for (int g = 0; g < 4; g++) {
                uint32_t r0, r1, r2, r3;
                uint32_t wA = sb + SM_WH(s) + wOff + g * (16 * A_STRIDE) + ko;
                ldsm4(r0, r1, r2, r3, wA);
                whf[2 * g][0] = r0; whf[2 * g][1] = r1;
                whf[2 * g + 1][0] = r2; whf[2 * g + 1][1] = r3;
                uint32_t wL = sb + SM_WL(s) + wOff + g * (16 * A_STRIDE) + ko;
                ldsm4(r0, r1, r2, r3, wL);
                wlf[2 * g][0] = r0; wlf[2 * g][1] = r1;
                wlf[2 * g + 1][0] = r2; wlf[2 * g + 1][1] = r3;
            }
#pragma unroll
            for (int mt = 0; mt < 2; mt++)
#pragma unroll
                for (int nt = 0; nt < 8; nt++) {
                    mma16816(acc[mt][nt], ahf[mt], whf[nt]);   // Ah*Wh
                    mma16816(acc[mt][nt], ahf[mt], wlf[nt]);   // Ah*Wl
                    mma16816(acc[mt][nt], alf[mt], whf[nt]);   // Al*Wh
                }
        }
        __syncthreads();
    }

    // ---- epilogue: +bias, direct fp32 stores ----
    const int r0base = half * 128 + wid * 32 + (lane >> 2);
    const int coff   = (lane & 3) * 2;
#pragma unroll
    for (int mt = 0; mt < 2; mt++) {
#pragma unroll
        for (int nt = 0; nt < 8; nt++) {
            const int cb = nt * 8 + coff;
            const float b0 = s_bias[cb], b1 = s_bias[cb + 1];
            const int ra = r0base + mt * 16;
            float* y0p = Y + ((size_t)t * BATCH + ra) * NY + cb;
            float* y1p = Y + ((size_t)t * BATCH + ra + 8) * NY + cb;
            float2 v0 = make_float2(acc[mt][nt][0] + b0, acc[mt][nt][1] + b1);
            float2 v1 = make_float2(acc[mt][nt][2] + b0, acc[mt][nt][3] + b1);
            *(float2*)y0p = v0;
            *(float2*)y1p = v1;
        }
    }
}

extern "C" void kernel_launch(void* const* d_in, const int* in_sizes, int n_in,
                              void* d_out, int out_size) {
    (void)in_sizes; (void)n_in; (void)out_size;
    const float* y0  = (const float*)d_in[0];
    const float* U   = (const float*)d_in[1];
    const float* lr  = (const float*)d_in[2];
    const float* li  = (const float*)d_in[3];
    const float* B   = (const float*)d_in[4];
    const float* Wyx = (const float*)d_in[5];
    const float* byx = (const float*)d_in[6];
    const float* Wxy = (const float*)d_in[7];
    const float* bxy = (const float*)d_in[8];
    float* Y = (float*)d_out;

    static bool attr_done = false;
    if (!attr_done) {
        cudaFuncSetAttribute(k3_mma, cudaFuncAttributeMaxDynamicSharedMemorySize, SMEM_K3);
        attr_done = true;
    }

    k0_wsplit<<<32, 256>>>(Wxy);
    k2_scan<<<2 * BATCH, 128>>>(U, lr, li, B, y0, Wyx, byx);
    k3_mma<<<(T_STEPS + 1) * 2, 128, SMEM_K3>>>(bxy, Y);
}